// round 14
// baseline (speedup 1.0000x reference)
#include <cuda_runtime.h>
#include <cuda_fp16.h>
#include <math.h>
#include <stdint.h>

// ---------------- problem constants ----------------
constexpr int NB   = 8;        // batch
constexpr int LRAW = 131072;
constexpr int NL1  = 32768;    // after pool1
constexpr int NL2  = 8192;     // after pool2
constexpr int NS   = 2048;     // seq len
constexpr int ND   = 256;      // model dim
constexpr int NH   = 8;        // heads
constexpr int NDH  = 32;       // head dim
constexpr int NM   = 128;      // kernel-map dim
constexpr int NFF  = 1024;
constexpr int NBS  = NB * NS;  // 16384
constexpr int KV_SPLITS = 8;

// packed-weight scratch layout (kp-words, per level), both layers contiguous per weight
constexpr int KP_SMALL = 2 * (ND / 2) * ND;     // Wq/Wk/Wv/Wo: 65536
constexpr int KP_W1    = 2 * (ND / 2) * NFF;    // 262144
constexpr int KP_W2    = 2 * (NFF / 2) * ND;    // 262144
constexpr int OFF_WQ = 0;
constexpr int OFF_WK = OFF_WQ + KP_SMALL;
constexpr int OFF_WV = OFF_WK + KP_SMALL;
constexpr int OFF_WO = OFF_WV + KP_SMALL;
constexpr int OFF_W1 = OFF_WO + KP_SMALL;
constexpr int OFF_W2 = OFF_W1 + KP_W1;
constexpr int TOT_KP = OFF_W2 + KP_W2;          // 786432

// ---------------- device scratch (no allocs allowed) ----------------
__device__ float g_h1 [NB * NL1 * 8];
__device__ float g_h2 [NB * NL2 * 16];
__device__ float g_ain[NBS * ND];
__device__ float g_q  [NBS * ND];
__device__ float g_k  [NBS * ND];
__device__ float g_v  [NBS * ND];
__device__ float g_qt [(size_t)NBS * NH * NM];
__device__ float g_kt [(size_t)NBS * NH * NM];
__device__ float g_kv [NB * NH * NM * NDH];
__device__ float g_kvp[KV_SPLITS * NB * NH * NM * NDH];
__device__ float g_o  [NBS * ND];
__device__ float g_mid[(size_t)NBS * NFF];
__device__ uint32_t g_wh[TOT_KP];
__device__ uint32_t g_wm[TOT_KP];
__device__ uint32_t g_wl[TOT_KP];

// ---------------- mma helpers ----------------
__device__ __forceinline__ uint32_t smem_u32(const void* p) {
    uint32_t a;
    asm("{ .reg .u64 t; cvta.to.shared.u64 t, %1; cvt.u32.u64 %0, t; }" : "=r"(a) : "l"(p));
    return a;
}
__device__ __forceinline__ void mma_f16(float* c, const uint32_t* a, const uint32_t* b) {
    asm volatile(
        "mma.sync.aligned.m16n8k16.row.col.f32.f16.f16.f32 "
        "{%0,%1,%2,%3}, {%4,%5,%6,%7}, {%8,%9}, {%0,%1,%2,%3};"
        : "+f"(c[0]), "+f"(c[1]), "+f"(c[2]), "+f"(c[3])
        : "r"(a[0]), "r"(a[1]), "r"(a[2]), "r"(a[3]), "r"(b[0]), "r"(b[1]));
}
__device__ __forceinline__ uint32_t punh2(__half2 h) {
    return *reinterpret_cast<uint32_t*>(&h);
}
// scaled 3-level split: x = h + (m/2048) + (l/2048^2); residuals stored at ~|x| magnitude.
__device__ __forceinline__ void split3s(float x, float y, uint32_t* o0, uint32_t* o1, uint32_t* o2) {
    __half2 h = __floats2half2_rn(x, y);
    float2 hf = __half22float2(h);
    float rx = (x - hf.x) * 2048.0f, ry = (y - hf.y) * 2048.0f;
    __half2 m = __floats2half2_rn(rx, ry);
    float2 mf = __half22float2(m);
    __half2 l = __floats2half2_rn((rx - mf.x) * 2048.0f, (ry - mf.y) * 2048.0f);
    *o0 = punh2(h); *o1 = punh2(m); *o2 = punh2(l);
}
// scaled 2-level split (same h,m as split3s)
__device__ __forceinline__ void split2s(float x, float y, uint32_t* o0, uint32_t* o1) {
    __half2 h = __floats2half2_rn(x, y);
    float2 hf = __half22float2(h);
    __half2 m = __floats2half2_rn((x - hf.x) * 2048.0f, (y - hf.y) * 2048.0f);
    *o0 = punh2(h); *o1 = punh2(m);
}
#define CP_ASYNC16(dst, src) \
    asm volatile("cp.async.cg.shared.global [%0], [%1], 16;" :: "r"(dst), "l"(src))
#define CP_COMMIT() asm volatile("cp.async.commit_group;" ::: "memory")
#define CP_WAIT1()  asm volatile("cp.async.wait_group 1;" ::: "memory")
#define CP_WAIT0()  asm volatile("cp.async.wait_group 0;" ::: "memory")

// ---------------- mega weight pre-split: all 6 weights x 2 layers in one launch ----------
__global__ void wsplit_all(const float* __restrict__ Wq, const float* __restrict__ Wk,
                           const float* __restrict__ Wv, const float* __restrict__ Wo,
                           const float* __restrict__ W1, const float* __restrict__ W2,
                           uint32_t* __restrict__ h, uint32_t* __restrict__ m,
                           uint32_t* __restrict__ l) {
    int idx = blockIdx.x * blockDim.x + threadIdx.x;
    if (idx >= TOT_KP) return;
    const float* src; int local, K, N;
    if (idx < OFF_WK)      { src = Wq; local = idx - OFF_WQ; K = ND;  N = ND;  }
    else if (idx < OFF_WV) { src = Wk; local = idx - OFF_WK; K = ND;  N = ND;  }
    else if (idx < OFF_WO) { src = Wv; local = idx - OFF_WV; K = ND;  N = ND;  }
    else if (idx < OFF_W1) { src = Wo; local = idx - OFF_WO; K = ND;  N = ND;  }
    else if (idx < OFF_W2) { src = W1; local = idx - OFF_W1; K = ND;  N = NFF; }
    else                   { src = W2; local = idx - OFF_W2; K = NFF; N = ND;  }
    int lsz = (K >> 1) * N;
    int layer = local / lsz, rem = local - layer * lsz;
    int kp = rem / N, n = rem - kp * N;
    const float* Wb = src + (size_t)layer * K * N;
    float x = Wb[(size_t)(2 * kp) * N + n];
    float y = Wb[(size_t)(2 * kp + 1) * N + n];
    split3s(x, y, &h[idx], &m[idx], &l[idx]);
}

// ------- split-fp16 GEMM: A split in-loop, W pre-split in gmem (round-11 config) -------
// CTA 128x64, 8 warps (4m x 2n), warp tile 32x32. K-chunk 32 (2 ksteps of 16).
constexpr int GA_STRIDE = 40;                         // A smem row stride (floats)
constexpr int GA_FLOATS = 128 * GA_STRIDE;            // 5120
constexpr int GBW       = 68;                         // B packed row stride (words)
constexpr int GB_LVLW   = 16 * GBW;                   // 1088 words per level per buf
constexpr float INV2048 = 1.0f / 2048.0f;
constexpr int GT_SMEM3 = (2 * GA_FLOATS + 2 * 3 * GB_LVLW) * 4;   // 67072 B
constexpr int GT_SMEM2 = (2 * GA_FLOATS + 2 * 2 * GB_LVLW) * 4;   // 58368 B

template <int LV, bool RELU, bool ADD>
__global__ void __launch_bounds__(256, LV == 2 ? 2 : 1) gemm_split(
        const float* __restrict__ A,
        const uint32_t* __restrict__ Wh, const uint32_t* __restrict__ Wm,
        const uint32_t* __restrict__ Wl,
        const float* __restrict__ bias, const float* __restrict__ Cin,
        float* __restrict__ C, int Ndim, int Kdim) {
    extern __shared__ uint32_t smw[];
    float* smA = (float*)smw;
    const uint32_t sbase = smem_u32(smw);
    const int BOFF = 2 * GA_FLOATS;

    const int tid = threadIdx.x, wid = tid >> 5, lane = tid & 31;
    const int warpM = wid >> 1, warpN = wid & 1;
    const int m0 = blockIdx.y * 128, n0 = blockIdx.x * 64;
    const int nch = Kdim >> 5;
    const int lr = lane >> 2, lc = lane & 3;

    float acc0[2][4][4], acc1[2][4][4], acc2[2][4][4];
#pragma unroll
    for (int i = 0; i < 2; i++)
#pragma unroll
        for (int j = 0; j < 4; j++)
#pragma unroll
            for (int r = 0; r < 4; r++) {
                acc0[i][j][r] = 0.f; acc1[i][j][r] = 0.f;
                if (LV == 3) acc2[i][j][r] = 0.f;
            }

    const int a_row = tid >> 1, a_c4 = tid & 1;       // A: 128 rows, 2 float4 per thread
    const int b_kp = tid >> 4, b_seg = tid & 15;      // B: 16 kp rows x 16 segs of 4 words

    auto load_chunk = [&](int c, int buf) {
        const float* Ap = A + (size_t)(m0 + a_row) * Kdim + c * 32;
        const uint32_t abase = sbase + (buf * GA_FLOATS + a_row * GA_STRIDE) * 4;
        CP_ASYNC16(abase + (a_c4 * 4) * 4,       Ap + a_c4 * 4);
        CP_ASYNC16(abase + ((a_c4 + 2) * 4) * 4, Ap + (a_c4 + 2) * 4);
        CP_ASYNC16(abase + ((a_c4 + 4) * 4) * 4, Ap + (a_c4 + 4) * 4);
        CP_ASYNC16(abase + ((a_c4 + 6) * 4) * 4, Ap + (a_c4 + 6) * 4);
        const size_t bsrc = (size_t)(c * 16 + b_kp) * Ndim + n0 + b_seg * 4;
        const uint32_t bb = sbase + (BOFF + buf * LV * GB_LVLW + b_kp * GBW + b_seg * 4) * 4;
        CP_ASYNC16(bb, Wh + bsrc);
        CP_ASYNC16(bb + GB_LVLW * 4, Wm + bsrc);
        if (LV == 3) CP_ASYNC16(bb + 2 * GB_LVLW * 4, Wl + bsrc);
        CP_COMMIT();
    };

    load_chunk(0, 0);

    for (int c = 0; c < nch; c++) {
        const int buf = c & 1;
        if (c + 1 < nch) { load_chunk(c + 1, buf ^ 1); CP_WAIT1(); }
        else             { CP_WAIT0(); }
        __syncthreads();

        const float* As = smA + buf * GA_FLOATS;
        const uint32_t* Bs = smw + BOFF + buf * LV * GB_LVLW;
#pragma unroll
        for (int ks = 0; ks < 2; ks++) {
            const int kb = ks * 16;
            uint32_t af[3][2][4];
#pragma unroll
            for (int mi = 0; mi < 2; mi++) {
                const int m = warpM * 32 + mi * 16 + lr;
                const float* ap = As + m * GA_STRIDE + kb + 2 * lc;
                float2 x0 = *(const float2*)(ap);
                float2 x1 = *(const float2*)(ap + 8 * GA_STRIDE);
                float2 x2 = *(const float2*)(ap + 8);
                float2 x3 = *(const float2*)(ap + 8 * GA_STRIDE + 8);
                if (LV == 3) {
                    split3s(x0.x, x0.y, &af[0][mi][0], &af[1][mi][0], &af[2][mi][0]);
                    split3s(x1.x, x1.y, &af[0][mi][1], &af[1][mi][1], &af[2][mi][1]);
                    split3s(x2.x, x2.y, &af[0][mi][2], &af[1][mi][2], &af[2][mi][2]);
                    split3s(x3.x, x3.y, &af[0][mi][3], &af[1][mi][3], &af[2][mi][3]);
                } else {
                    split2s(x0.x, x0.y, &af[0][mi][0], &af[1][mi][0]);
                    split2s(x1.x, x1.y, &af[0][mi][1], &af[1][mi][1]);
                    split2s(x2.x, x2.y, &af[0][mi][2], &af[1][mi][2]);
                    split2s(x3.x, x3.y, &af[0][mi][3], &af[1][mi][3]);
                }
            }
            const int kp0 = ks * 8 + lc;
#pragma unroll
            for (int ni = 0; ni < 4; ni++) {
                const int n = warpN * 32 + ni * 8 + lr;
                uint32_t bf[3][2];
#pragma unroll
                for (int lev = 0; lev < LV; lev++) {
                    const uint32_t* p = Bs + lev * GB_LVLW + n;
                    bf[lev][0] = p[kp0 * GBW];
                    bf[lev][1] = p[(kp0 + 4) * GBW];
                }
#pragma unroll
                for (int mi = 0; mi < 2; mi++) {
                    mma_f16(acc0[mi][ni], af[0][mi], bf[0]);       // h*H   (x1)
                    mma_f16(acc1[mi][ni], af[0][mi], bf[1]);       // h*M   (x2^-11)
                    mma_f16(acc1[mi][ni], af[1][mi], bf[0]);       // m*H   (x2^-11)
                    if (LV == 3) {
                        mma_f16(acc2[mi][ni], af[0][mi], bf[2]);   // h*L   (x2^-22)
                        mma_f16(acc2[mi][ni], af[1][mi], bf[1]);   // m*M   (x2^-22)
                        mma_f16(acc2[mi][ni], af[2][mi], bf[0]);   // l*H   (x2^-22)
                    }
                }
            }
        }
        __syncthreads();
    }

    // epilogue
#pragma unroll
    for (int mi = 0; mi < 2; mi++) {
#pragma unroll
        for (int ni = 0; ni < 4; ni++) {
            const int col = n0 + warpN * 32 + ni * 8 + lc * 2;
            const float bx = __ldg(&bias[col]), by = __ldg(&bias[col + 1]);
#pragma unroll
            for (int h = 0; h < 2; h++) {
                const int row = m0 + warpM * 32 + mi * 16 + lr + h * 8;
                float r1x = acc1[mi][ni][h*2+0], r1y = acc1[mi][ni][h*2+1];
                if (LV == 3) {
                    r1x = fmaf(acc2[mi][ni][h*2+0], INV2048, r1x);
                    r1y = fmaf(acc2[mi][ni][h*2+1], INV2048, r1y);
                }
                float vx = fmaf(r1x, INV2048, acc0[mi][ni][h*2+0]) + bx;
                float vy = fmaf(r1y, INV2048, acc0[mi][ni][h*2+1]) + by;
                if (RELU) { vx = fmaxf(vx, 0.f); vy = fmaxf(vy, 0.f); }
                if (ADD) {
                    const float2 ci = *(const float2*)(Cin + (size_t)row * Ndim + col);
                    vx += ci.x; vy += ci.y;
                }
                *(float2*)(C + (size_t)row * Ndim + col) = make_float2(vx, vy);
            }
        }
    }
}

// ---------------- conv stem ----------------
__global__ void conv1_pool(const float* __restrict__ x, const float* __restrict__ w,
                           const float* __restrict__ bias, float* __restrict__ out) {
    __shared__ float ws[88];
    __shared__ float bsm[8];
    if (threadIdx.x < 88) ws[threadIdx.x] = w[threadIdx.x];
    if (threadIdx.x < 8)  bsm[threadIdx.x] = bias[threadIdx.x];
    __syncthreads();
    int idx = blockIdx.x * blockDim.x + threadIdx.x;
    if (idx >= NB * NL1) return;
    int b = idx >> 15, lo = idx & (NL1 - 1);
    const float* xb = x + (size_t)b * LRAW;
    float acc[8] = {0.f,0.f,0.f,0.f,0.f,0.f,0.f,0.f};
#pragma unroll
    for (int p = 0; p < 4; p++) {
        int l = 4 * lo + p;
        float conv[8];
#pragma unroll
        for (int c = 0; c < 8; c++) conv[c] = bsm[c];
#pragma unroll
        for (int j = 0; j < 11; j++) {
            int li = l + j - 5;
            float xv = (li >= 0 && li < LRAW) ? __ldg(&xb[li]) : 0.f;
#pragma unroll
            for (int c = 0; c < 8; c++) conv[c] += xv * ws[j * 8 + c];
        }
#pragma unroll
        for (int c = 0; c < 8; c++) acc[c] += fmaxf(conv[c], 0.f);
    }
#pragma unroll
    for (int c = 0; c < 8; c++) out[(size_t)idx * 8 + c] = acc[c] * 0.25f;
}

__global__ void conv2_pool(const float* __restrict__ in, const float* __restrict__ w,
                           const float* __restrict__ bias, float* __restrict__ out) {
    __shared__ float ws[384];
    __shared__ float bsm[16];
    for (int i = threadIdx.x; i < 384; i += blockDim.x) ws[i] = w[i];
    if (threadIdx.x < 16) bsm[threadIdx.x] = bias[threadIdx.x];
    __syncthreads();
    int idx = blockIdx.x * blockDim.x + threadIdx.x;
    if (idx >= NB * NL2) return;
    int b = idx >> 13, lo = idx & (NL2 - 1);
    float acc[16];
#pragma unroll
    for (int c = 0; c < 16; c++) acc[c] = 0.f;
#pragma unroll
    for (int p = 0; p < 4; p++) {
        int l = 4 * lo + p;
        float conv[16];
#pragma unroll
        for (int c = 0; c < 16; c++) conv[c] = bsm[c];
#pragma unroll
        for (int j = 0; j < 3; j++) {
            int li = l + j - 1;
            if (li >= 0 && li < NL1) {
                const float* row = in + ((size_t)b * NL1 + li) * 8;
#pragma unroll
                for (int ci = 0; ci < 8; ci++) {
                    float xv = __ldg(&row[ci]);
#pragma unroll
                    for (int co = 0; co < 16; co++) conv[co] += xv * ws[(j * 8 + ci) * 16 + co];
                }
            }
        }
#pragma unroll
        for (int c = 0; c < 16; c++) acc[c] += fmaxf(conv[c], 0.f);
    }
#pragma unroll
    for (int c = 0; c < 16; c++) out[(size_t)idx * 16 + c] = acc[c] * 0.25f;
}

__global__ void conv3_pool(const float* __restrict__ in, const float* __restrict__ w,
                           const float* __restrict__ bias, float* __restrict__ out) {
    int blk = blockIdx.x;
    int b = blk >> 11, lo = blk & (NS - 1);
    int co = threadIdx.x;
    __shared__ float insm[6 * 16];
    if (threadIdx.x < 96) {
        int rr = threadIdx.x >> 4, ci = threadIdx.x & 15;
        int li = 4 * lo - 1 + rr;
        insm[threadIdx.x] = (li >= 0 && li < NL2) ? in[((size_t)b * NL2 + li) * 16 + ci] : 0.f;
    }
    float wreg[48];
#pragma unroll
    for (int i = 0; i < 48; i++) wreg[i] = __ldg(&w[(size_t)i * ND + co]);
    float bv = __ldg(&bias[co]);
    __syncthreads();
    float acc = 0.f;
#pragma unroll
    for (int p = 0; p < 4; p++) {
        float conv = bv;
#pragma unroll
        for (int j = 0; j < 3; j++) {
#pragma unroll
            for (int ci = 0; ci < 16; ci++)
                conv += insm[(p + j) * 16 + ci] * wreg[j * 16 + ci];
        }
        acc += fmaxf(conv, 0.f);
    }
    out[((size_t)b * NS + lo) * ND + co] = acc * 0.25f;
}

// ---------------- LayerCentering ----------------
__global__ void lc_kernel(const float* __restrict__ src, float* __restrict__ dst) {
    int row = blockIdx.x;
    int tid = threadIdx.x;
    float v = src[(size_t)row * ND + tid];
    float s = v;
#pragma unroll
    for (int off = 16; off; off >>= 1) s += __shfl_down_sync(0xffffffffu, s, off);
    __shared__ float red[8];
    __shared__ float meansh;
    if ((tid & 31) == 0) red[tid >> 5] = s;
    __syncthreads();
    if (tid == 0) {
        float t = 0.f;
#pragma unroll
        for (int i = 0; i < 8; i++) t += red[i];
        meansh = t * (1.0f / ND);
    }
    __syncthreads();
    dst[(size_t)row * ND + tid] = v - meansh;
}

// ---------------- fourier features + exponential positional modulation ----------------
__global__ void fourier_kernel(const float* __restrict__ q, const float* __restrict__ k,
                               const float* __restrict__ omega, const float* __restrict__ gamma,
                               float* __restrict__ qt, float* __restrict__ kt) {
    int bs = blockIdx.x;
    int tid = threadIdx.x;
    __shared__ float qrow[ND], krow[ND];
    qrow[tid] = q[(size_t)bs * ND + tid];
    krow[tid] = k[(size_t)bs * ND + tid];
    __syncthreads();
    int h = tid >> 5, lane = tid & 31;
    const float* om = omega + h * NDH * (NM / 2);
    float pq0 = 0.f, pq1 = 0.f, pk0 = 0.f, pk1 = 0.f;
#pragma unroll 8
    for (int d = 0; d < NDH; d++) {
        float qd = qrow[h * NDH + d], kd = krow[h * NDH + d];
        float o0 = __ldg(&om[d * 64 + lane]);
        float o1 = __ldg(&om[d * 64 + lane + 32]);
        pq0 += qd * o0; pq1 += qd * o1;
        pk0 += kd * o0; pk1 += kd * o1;
    }
    int s = bs & (NS - 1);
    float t = s * (1.0f / (NS - 1));
    float g = __ldg(&gamma[h]);
    float sl0 = 2.0f - lane * (1.0f / 32.0f);
    float sl1 = 2.0f - (lane + 32) * (1.0f / 32.0f);
    const float invs = 0.08838834764831845f;
    float a0 = g * t * sl0, a1 = g * t * sl1;
    float b0 = g * (1.0f - t) * sl0, b1 = g * (1.0f - t) * sl1;
    size_t base = ((size_t)bs * NH + h) * NM;
    qt[base + lane]      = cosf(pq0) * invs * expf(a0);
    qt[base + lane + 32] = cosf(pq1) * invs * expf(a1);
    qt[base + lane + 64] = sinf(pq0) * invs * expf(b0);
    qt[base + lane + 96] = sinf(pq1) * invs * expf(b1);
    kt[base + lane]      = cosf(pk0) * invs * expf(-a0);
    kt[base + lane + 32] = cosf(pk1) * invs * expf(-a1);
    kt[base + lane + 64] = sinf(pk0) * invs * expf(-b0);
    kt[base + lane + 96] = sinf(pk1) * invs * expf(-b1);
}

// ---------------- kv = sum_s kt^T v (split over S, deterministic) ----------------
__global__ void kv_partial(const float* __restrict__ kt, const float* __restrict__ v,
                           float* __restrict__ kvp) {
    int bh = blockIdx.x;
    int b = bh >> 3, h = bh & 7;
    int chunk = blockIdx.y;
    int m = threadIdx.x;
    __shared__ float vs[64 * 32];
    float acc[32];
#pragma unroll
    for (int e = 0; e < 32; e++) acc[e] = 0.f;
    int sbase = chunk * (NS / KV_SPLITS);
    for (int s0 = sbase; s0 < sbase + NS / KV_SPLITS; s0 += 64) {
        __syncthreads();
        for (int idx = threadIdx.x; idx < 64 * 32; idx += 128) {
            int i = idx >> 5, e = idx & 31;
            vs[idx] = v[((size_t)(b * NS + s0 + i)) * ND + h * NDH + e];
        }
        __syncthreads();
#pragma unroll 4
        for (int i = 0; i < 64; i++) {
            float kval = kt[(((size_t)(b * NS + s0 + i)) * NH + h) * NM + m];
#pragma unroll
            for (int e = 0; e < 32; e++) acc[e] += kval * vs[i * 32 + e];
        }
    }
    float* dst = kvp + (((size_t)chunk * (NB * NH) + bh) * NM + m) * NDH;
#pragma unroll
    for (int e = 0; e < 32; e++) dst[e] = acc[e];
}

__global__ void kv_reduce(const float* __restrict__ kvp, float* __restrict__ kv) {
    int idx = blockIdx.x * blockDim.x + threadIdx.x;
    if (idx >= NB * NH * NM * NDH) return;
    float s = 0.f;
#pragma unroll
    for (int c = 0; c < KV_SPLITS; c++) s += kvp[(size_t)c * (NB * NH * NM * NDH) + idx];
    kv[idx] = s;
}

// ---------------- o = qt @ kv ----------------
__global__ void attn_o(const float* __restrict__ qt, const float* __restrict__ kv,
                       float* __restrict__ o) {
    int bh = blockIdx.x;
    int b = bh >> 3, h = bh & 7;
    int s0 = blockIdx.y * 32;
    __shared__ float kvs[NM * NDH];
    __shared__ float qsm[32 * NM];
    for (int idx = threadIdx.x; idx < NM * NDH; idx += 256)
        kvs[idx] = kv[(size_t)bh * (NM * NDH) + idx];
    for (int idx = threadIdx.x; idx < 32 * NM; idx += 256) {
        int si = idx >> 7, m = idx & 127;
        qsm[idx] = qt[(((size_t)(b * NS + s0 + si)) * NH + h) * NM + m];
    }
    __syncthreads();
    int e = threadIdx.x & 31, sg = threadIdx.x >> 5;
    float acc[4] = {0.f, 0.f, 0.f, 0.f};
#pragma unroll 4
    for (int m = 0; m < NM; m++) {
        float kval = kvs[m * 32 + e];
#pragma unroll
        for (int i = 0; i < 4; i++) acc[i] += qsm[(sg * 4 + i) * NM + m] * kval;
    }
#pragma unroll
    for (int i = 0; i < 4; i++)
        o[((size_t)(b * NS + s0 + sg * 4 + i)) * ND + h * NDH + e] = acc[i];
}

// ---------------- host launcher ----------------
extern "C" void kernel_launch(void* const* d_in, const int* in_sizes, int n_in,
                              void* d_out, int out_size) {
    const float* x     = (const float*)d_in[0];
    const float* cw0   = (const float*)d_in[1];
    const float* cb0   = (const float*)d_in[2];
    const float* cw1   = (const float*)d_in[3];
    const float* cb1   = (const float*)d_in[4];
    const float* cw2   = (const float*)d_in[5];
    const float* cb2   = (const float*)d_in[6];
    const float* Wq    = (const float*)d_in[7];
    const float* bq    = (const float*)d_in[8];
    const float* Wk    = (const float*)d_in[9];
    const float* bk    = (const float*)d_in[10];
    const float* Wv    = (const float*)d_in[11];
    const float* bv    = (const float*)d_in[12];
    const float* Wo    = (const float*)d_in[13];
    const float* bo    = (const float*)d_in[14];
    const float* omega = (const float*)d_in[15];
    const float* gamma = (const float*)d_in[16];
    const float* W1    = (const float*)d_in[17];
    const float* b1    = (const float*)d_in[18];
    const float* W2    = (const float*)d_in[19];
    const float* b2    = (const float*)d_in[20];
    float* hout = (float*)d_out;

    float *p_h1, *p_h2, *p_ain, *p_q, *p_k, *p_v, *p_qt, *p_kt, *p_kv, *p_kvp, *p_o, *p_mid;
    uint32_t *p_wh, *p_wm, *p_wl;
    cudaGetSymbolAddress((void**)&p_h1,  g_h1);
    cudaGetSymbolAddress((void**)&p_h2,  g_h2);
    cudaGetSymbolAddress((void**)&p_ain, g_ain);
    cudaGetSymbolAddress((void**)&p_q,   g_q);
    cudaGetSymbolAddress((void**)&p_k,   g_k);
    cudaGetSymbolAddress((void**)&p_v,   g_v);
    cudaGetSymbolAddress((void**)&p_qt,  g_qt);
    cudaGetSymbolAddress((void**)&p_kt,  g_kt);
    cudaGetSymbolAddress((void**)&p_kv,  g_kv);
    cudaGetSymbolAddress((void**)&p_kvp, g_kvp);
    cudaGetSymbolAddress((void**)&p_o,   g_o);
    cudaGetSymbolAddress((void**)&p_mid, g_mid);
    cudaGetSymbolAddress((void**)&p_wh,  g_wh);
    cudaGetSymbolAddress((void**)&p_wm,  g_wm);
    cudaGetSymbolAddress((void**)&p_wl,  g_wl);

    cudaFuncSetAttribute(gemm_split<3, false, false>, cudaFuncAttributeMaxDynamicSharedMemorySize, GT_SMEM3);
    cudaFuncSetAttribute(gemm_split<3, false, true>,  cudaFuncAttributeMaxDynamicSharedMemorySize, GT_SMEM3);
    cudaFuncSetAttribute(gemm_split<3, true, false>,  cudaFuncAttributeMaxDynamicSharedMemorySize, GT_SMEM3);
    cudaFuncSetAttribute(gemm_split<2, false, false>, cudaFuncAttributeMaxDynamicSharedMemorySize, GT_SMEM2);
    cudaFuncSetAttribute(gemm_split<2, false, true>,  cudaFuncAttributeMaxDynamicSharedMemorySize, GT_SMEM2);
    cudaFuncSetAttribute(gemm_split<2, true, false>,  cudaFuncAttributeMaxDynamicSharedMemorySize, GT_SMEM2);

    // all weight splits in one launch (both layers, all 6 weights)
    wsplit_all<<<(TOT_KP + 255) / 256, 256>>>(Wq, Wk, Wv, Wo, W1, W2, p_wh, p_wm, p_wl);

    // conv stem
    conv1_pool<<<(NB * NL1 + 255) / 256, 256>>>(x, cw0, cb0, p_h1);
    conv2_pool<<<(NB * NL2 + 255) / 256, 256>>>(p_h1, cw1, cb1, p_h2);
    conv3_pool<<<NB * NS, 256>>>(p_h2, cw2, cb2, hout);

    dim3 gN256(4, NBS / 128);      // N=256: 4 n-tiles of 64 x 128 m-tiles of 128
    dim3 gN1024(16, NBS / 128);    // N=1024

    constexpr int LSZ_S  = (ND / 2) * ND;     // per-layer kp size, small weights
    constexpr int LSZ_W1 = (ND / 2) * NFF;
    constexpr int LSZ_W2 = (NFF / 2) * ND;

    for (int l = 0; l < 2; l++) {
        const int oQ = OFF_WQ + l * LSZ_S, oK = OFF_WK + l * LSZ_S;
        const int oV = OFF_WV + l * LSZ_S, oO = OFF_WO + l * LSZ_S;
        const int o1 = OFF_W1 + l * LSZ_W1, o2 = OFF_W2 + l * LSZ_W2;
        const float* om_l = omega + (size_t)l * NH * NDH * (NM / 2);
        const float* g_l  = gamma + (size_t)l * NH;

        lc_kernel<<<NBS, ND>>>(hout, p_ain);

        gemm_split<3, false, false><<<gN256, 256, GT_SMEM3>>>(p_ain, p_wh + oQ, p_wm + oQ, p_wl + oQ, bq + l * ND, nullptr, p_q, ND, ND);
        gemm_split<3, false, false><<<gN256, 256, GT_SMEM3>>>(p_ain, p_wh + oK, p_wm + oK, p_wl + oK, bk + l * ND, nullptr, p_k, ND, ND);
        if (l == 0)
            gemm_split<3, false, false><<<gN256, 256, GT_SMEM3>>>(p_ain, p_wh + oV, p_wm + oV, p_wl + oV, bv + l * ND, nullptr, p_v, ND, ND);
        else
            gemm_split<2, false, false><<<gN256, 256, GT_SMEM2>>>(p_ain, p_wh + oV, p_wm + oV, p_wl + oV, bv + l * ND, nullptr, p_v, ND, ND);

        fourier_kernel<<<NBS, 256>>>(p_q, p_k, om_l, g_l, p_qt, p_kt);

        kv_partial<<<dim3(NB * NH, KV_SPLITS), 128>>>(p_kt, p_v, p_kvp);
        kv_reduce<<<(NB * NH * NM * NDH + 255) / 256, 256>>>(p_kvp, p_kv);

        attn_o<<<dim3(NB * NH, NS / 32), 256>>>(p_qt, p_kv, p_o);

        if (l == 0) {
            gemm_split<3, false, true><<<gN256, 256, GT_SMEM3>>>(p_o, p_wh + oO, p_wm + oO, p_wl + oO, bo + l * ND, hout, hout, ND, ND);
            lc_kernel<<<NBS, ND>>>(hout, p_ain);
            // layer-0 FF1: LV2 (error contribution ~0.5e-3 in quadrature, budget-checked)
            gemm_split<2, true, false><<<gN1024, 256, GT_SMEM2>>>(p_ain, p_wh + o1, p_wm + o1, p_wl + o1, b1 + l * NFF, nullptr, p_mid, NFF, ND);
            gemm_split<3, false, true><<<gN256, 256, GT_SMEM3>>>(p_mid, p_wh + o2, p_wm + o2, p_wl + o2, b2 + l * ND, hout, hout, ND, NFF);
        } else {
            gemm_split<2, false, true><<<gN256, 256, GT_SMEM2>>>(p_o, p_wh + oO, p_wm + oO, p_wl + oO, bo + l * ND, hout, hout, ND, ND);
            lc_kernel<<<NBS, ND>>>(hout, p_ain);
            gemm_split<2, true, false><<<gN1024, 256, GT_SMEM2>>>(p_ain, p_wh + o1, p_wm + o1, p_wl + o1, b1 + l * NFF, nullptr, p_mid, NFF, ND);
            gemm_split<2, false, true><<<gN256, 256, GT_SMEM2>>>(p_mid, p_wh + o2, p_wm + o2, p_wl + o2, b2 + l * ND, hout, hout, ND, NFF);
        }
    }
}

// round 15
// speedup vs baseline: 1.1054x; 1.1054x over previous
#include <cuda_runtime.h>
#include <cuda_fp16.h>
#include <math.h>
#include <stdint.h>

// ---------------- problem constants ----------------
constexpr int NB   = 8;        // batch
constexpr int LRAW = 131072;
constexpr int NL1  = 32768;    // after pool1
constexpr int NL2  = 8192;     // after pool2
constexpr int NS   = 2048;     // seq len
constexpr int ND   = 256;      // model dim
constexpr int NH   = 8;        // heads
constexpr int NDH  = 32;       // head dim
constexpr int NM   = 128;      // kernel-map dim
constexpr int NFF  = 1024;
constexpr int NBS  = NB * NS;  // 16384
constexpr int KV_SPLITS = 8;

// packed-weight scratch layout (kp-words, per level), both layers contiguous per weight
constexpr int KP_SMALL = 2 * (ND / 2) * ND;     // Wq/Wk/Wv/Wo: 65536
constexpr int KP_W1    = 2 * (ND / 2) * NFF;    // 262144
constexpr int KP_W2    = 2 * (NFF / 2) * ND;    // 262144
constexpr int OFF_WQ = 0;
constexpr int OFF_WK = OFF_WQ + KP_SMALL;
constexpr int OFF_WV = OFF_WK + KP_SMALL;
constexpr int OFF_WO = OFF_WV + KP_SMALL;
constexpr int OFF_W1 = OFF_WO + KP_SMALL;
constexpr int OFF_W2 = OFF_W1 + KP_W1;
constexpr int TOT_KP = OFF_W2 + KP_W2;          // 786432

// ---------------- device scratch (no allocs allowed) ----------------
__device__ float g_h1 [NB * NL1 * 8];
__device__ float g_h2 [NB * NL2 * 16];
__device__ float g_ain[NBS * ND];
__device__ float g_q  [NBS * ND];
__device__ float g_k  [NBS * ND];
__device__ float g_v  [NBS * ND];
__device__ float g_qt [(size_t)NBS * NH * NM];
__device__ float g_kt [(size_t)NBS * NH * NM];
__device__ float g_kv [NB * NH * NM * NDH];
__device__ float g_kvp[KV_SPLITS * NB * NH * NM * NDH];
__device__ float g_o  [NBS * ND];
__device__ float g_mid[(size_t)NBS * NFF];
__device__ uint32_t g_wh[TOT_KP];
__device__ uint32_t g_wm[TOT_KP];
__device__ uint32_t g_wl[TOT_KP];

// ---------------- mma helpers ----------------
__device__ __forceinline__ uint32_t smem_u32(const void* p) {
    uint32_t a;
    asm("{ .reg .u64 t; cvta.to.shared.u64 t, %1; cvt.u32.u64 %0, t; }" : "=r"(a) : "l"(p));
    return a;
}
__device__ __forceinline__ void mma_f16(float* c, const uint32_t* a, const uint32_t* b) {
    asm volatile(
        "mma.sync.aligned.m16n8k16.row.col.f32.f16.f16.f32 "
        "{%0,%1,%2,%3}, {%4,%5,%6,%7}, {%8,%9}, {%0,%1,%2,%3};"
        : "+f"(c[0]), "+f"(c[1]), "+f"(c[2]), "+f"(c[3])
        : "r"(a[0]), "r"(a[1]), "r"(a[2]), "r"(a[3]), "r"(b[0]), "r"(b[1]));
}
__device__ __forceinline__ uint32_t punh2(__half2 h) {
    return *reinterpret_cast<uint32_t*>(&h);
}
// scaled 3-level split: x = h + (m/2048) + (l/2048^2); residuals stored at ~|x| magnitude.
__device__ __forceinline__ void split3s(float x, float y, uint32_t* o0, uint32_t* o1, uint32_t* o2) {
    __half2 h = __floats2half2_rn(x, y);
    float2 hf = __half22float2(h);
    float rx = (x - hf.x) * 2048.0f, ry = (y - hf.y) * 2048.0f;
    __half2 m = __floats2half2_rn(rx, ry);
    float2 mf = __half22float2(m);
    __half2 l = __floats2half2_rn((rx - mf.x) * 2048.0f, (ry - mf.y) * 2048.0f);
    *o0 = punh2(h); *o1 = punh2(m); *o2 = punh2(l);
}
// scaled 2-level split (same h,m as split3s)
__device__ __forceinline__ void split2s(float x, float y, uint32_t* o0, uint32_t* o1) {
    __half2 h = __floats2half2_rn(x, y);
    float2 hf = __half22float2(h);
    __half2 m = __floats2half2_rn((x - hf.x) * 2048.0f, (y - hf.y) * 2048.0f);
    *o0 = punh2(h); *o1 = punh2(m);
}
#define CP_ASYNC16(dst, src) \
    asm volatile("cp.async.cg.shared.global [%0], [%1], 16;" :: "r"(dst), "l"(src))
#define CP_COMMIT() asm volatile("cp.async.commit_group;" ::: "memory")
#define CP_WAIT1()  asm volatile("cp.async.wait_group 1;" ::: "memory")
#define CP_WAIT0()  asm volatile("cp.async.wait_group 0;" ::: "memory")

// ---------------- mega weight pre-split: all 6 weights x 2 layers in one launch ----------
__global__ void wsplit_all(const float* __restrict__ Wq, const float* __restrict__ Wk,
                           const float* __restrict__ Wv, const float* __restrict__ Wo,
                           const float* __restrict__ W1, const float* __restrict__ W2,
                           uint32_t* __restrict__ h, uint32_t* __restrict__ m,
                           uint32_t* __restrict__ l) {
    int idx = blockIdx.x * blockDim.x + threadIdx.x;
    if (idx >= TOT_KP) return;
    const float* src; int local, K, N;
    if (idx < OFF_WK)      { src = Wq; local = idx - OFF_WQ; K = ND;  N = ND;  }
    else if (idx < OFF_WV) { src = Wk; local = idx - OFF_WK; K = ND;  N = ND;  }
    else if (idx < OFF_WO) { src = Wv; local = idx - OFF_WV; K = ND;  N = ND;  }
    else if (idx < OFF_W1) { src = Wo; local = idx - OFF_WO; K = ND;  N = ND;  }
    else if (idx < OFF_W2) { src = W1; local = idx - OFF_W1; K = ND;  N = NFF; }
    else                   { src = W2; local = idx - OFF_W2; K = NFF; N = ND;  }
    int lsz = (K >> 1) * N;
    int layer = local / lsz, rem = local - layer * lsz;
    int kp = rem / N, n = rem - kp * N;
    const float* Wb = src + (size_t)layer * K * N;
    float x = Wb[(size_t)(2 * kp) * N + n];
    float y = Wb[(size_t)(2 * kp + 1) * N + n];
    split3s(x, y, &h[idx], &m[idx], &l[idx]);
}

// ------- split-fp16 GEMM: A split in-loop, W pre-split in gmem -------
// CTA 128x64, 8 warps (4m x 2n), warp tile 32x32. K-chunk 32 (2 ksteps of 16).
constexpr int GA_STRIDE = 40;                         // A smem row stride (floats)
constexpr int GA_FLOATS = 128 * GA_STRIDE;            // 5120
constexpr int GBW       = 68;                         // B packed row stride (words)
constexpr int GB_LVLW   = 16 * GBW;                   // 1088 words per level per buf
constexpr float INV2048 = 1.0f / 2048.0f;
constexpr int GT_SMEM3 = (2 * GA_FLOATS + 2 * 3 * GB_LVLW) * 4;   // 67072 B
constexpr int GT_SMEM2 = (2 * GA_FLOATS + 2 * 2 * GB_LVLW) * 4;   // 58368 B

template <int LV, bool RELU, bool ADD>
__global__ void __launch_bounds__(256, LV == 2 ? 2 : 1) gemm_split(
        const float* __restrict__ A,
        const uint32_t* __restrict__ Wh, const uint32_t* __restrict__ Wm,
        const uint32_t* __restrict__ Wl,
        const float* __restrict__ bias, const float* __restrict__ Cin,
        float* __restrict__ C, int Ndim, int Kdim) {
    extern __shared__ uint32_t smw[];
    float* smA = (float*)smw;
    const uint32_t sbase = smem_u32(smw);
    const int BOFF = 2 * GA_FLOATS;

    const int tid = threadIdx.x, wid = tid >> 5, lane = tid & 31;
    const int warpM = wid >> 1, warpN = wid & 1;
    const int m0 = blockIdx.y * 128, n0 = blockIdx.x * 64;
    const int nch = Kdim >> 5;
    const int lr = lane >> 2, lc = lane & 3;

    float acc0[2][4][4], acc1[2][4][4], acc2[2][4][4];
#pragma unroll
    for (int i = 0; i < 2; i++)
#pragma unroll
        for (int j = 0; j < 4; j++)
#pragma unroll
            for (int r = 0; r < 4; r++) {
                acc0[i][j][r] = 0.f; acc1[i][j][r] = 0.f;
                if (LV == 3) acc2[i][j][r] = 0.f;
            }

    const int a_row = tid >> 1, a_c4 = tid & 1;       // A: 128 rows, 2 float4 per thread
    const int b_kp = tid >> 4, b_seg = tid & 15;      // B: 16 kp rows x 16 segs of 4 words

    auto load_chunk = [&](int c, int buf) {
        const float* Ap = A + (size_t)(m0 + a_row) * Kdim + c * 32;
        const uint32_t abase = sbase + (buf * GA_FLOATS + a_row * GA_STRIDE) * 4;
        CP_ASYNC16(abase + (a_c4 * 4) * 4,       Ap + a_c4 * 4);
        CP_ASYNC16(abase + ((a_c4 + 2) * 4) * 4, Ap + (a_c4 + 2) * 4);
        CP_ASYNC16(abase + ((a_c4 + 4) * 4) * 4, Ap + (a_c4 + 4) * 4);
        CP_ASYNC16(abase + ((a_c4 + 6) * 4) * 4, Ap + (a_c4 + 6) * 4);
        const size_t bsrc = (size_t)(c * 16 + b_kp) * Ndim + n0 + b_seg * 4;
        const uint32_t bb = sbase + (BOFF + buf * LV * GB_LVLW + b_kp * GBW + b_seg * 4) * 4;
        CP_ASYNC16(bb, Wh + bsrc);
        CP_ASYNC16(bb + GB_LVLW * 4, Wm + bsrc);
        if (LV == 3) CP_ASYNC16(bb + 2 * GB_LVLW * 4, Wl + bsrc);
        CP_COMMIT();
    };

    load_chunk(0, 0);

    for (int c = 0; c < nch; c++) {
        const int buf = c & 1;
        if (c + 1 < nch) { load_chunk(c + 1, buf ^ 1); CP_WAIT1(); }
        else             { CP_WAIT0(); }
        __syncthreads();

        const float* As = smA + buf * GA_FLOATS;
        const uint32_t* Bs = smw + BOFF + buf * LV * GB_LVLW;
#pragma unroll
        for (int ks = 0; ks < 2; ks++) {
            const int kb = ks * 16;
            uint32_t af[3][2][4];
#pragma unroll
            for (int mi = 0; mi < 2; mi++) {
                const int m = warpM * 32 + mi * 16 + lr;
                const float* ap = As + m * GA_STRIDE + kb + 2 * lc;
                float2 x0 = *(const float2*)(ap);
                float2 x1 = *(const float2*)(ap + 8 * GA_STRIDE);
                float2 x2 = *(const float2*)(ap + 8);
                float2 x3 = *(const float2*)(ap + 8 * GA_STRIDE + 8);
                if (LV == 3) {
                    split3s(x0.x, x0.y, &af[0][mi][0], &af[1][mi][0], &af[2][mi][0]);
                    split3s(x1.x, x1.y, &af[0][mi][1], &af[1][mi][1], &af[2][mi][1]);
                    split3s(x2.x, x2.y, &af[0][mi][2], &af[1][mi][2], &af[2][mi][2]);
                    split3s(x3.x, x3.y, &af[0][mi][3], &af[1][mi][3], &af[2][mi][3]);
                } else {
                    split2s(x0.x, x0.y, &af[0][mi][0], &af[1][mi][0]);
                    split2s(x1.x, x1.y, &af[0][mi][1], &af[1][mi][1]);
                    split2s(x2.x, x2.y, &af[0][mi][2], &af[1][mi][2]);
                    split2s(x3.x, x3.y, &af[0][mi][3], &af[1][mi][3]);
                }
            }
            const int kp0 = ks * 8 + lc;
#pragma unroll
            for (int ni = 0; ni < 4; ni++) {
                const int n = warpN * 32 + ni * 8 + lr;
                uint32_t bf[3][2];
#pragma unroll
                for (int lev = 0; lev < LV; lev++) {
                    const uint32_t* p = Bs + lev * GB_LVLW + n;
                    bf[lev][0] = p[kp0 * GBW];
                    bf[lev][1] = p[(kp0 + 4) * GBW];
                }
#pragma unroll
                for (int mi = 0; mi < 2; mi++) {
                    mma_f16(acc0[mi][ni], af[0][mi], bf[0]);       // h*H   (x1)
                    mma_f16(acc1[mi][ni], af[0][mi], bf[1]);       // h*M   (x2^-11)
                    mma_f16(acc1[mi][ni], af[1][mi], bf[0]);       // m*H   (x2^-11)
                    if (LV == 3) {
                        mma_f16(acc2[mi][ni], af[0][mi], bf[2]);   // h*L   (x2^-22)
                        mma_f16(acc2[mi][ni], af[1][mi], bf[1]);   // m*M   (x2^-22)
                        mma_f16(acc2[mi][ni], af[2][mi], bf[0]);   // l*H   (x2^-22)
                    }
                }
            }
        }
        __syncthreads();
    }

    // epilogue
#pragma unroll
    for (int mi = 0; mi < 2; mi++) {
#pragma unroll
        for (int ni = 0; ni < 4; ni++) {
            const int col = n0 + warpN * 32 + ni * 8 + lc * 2;
            const float bx = __ldg(&bias[col]), by = __ldg(&bias[col + 1]);
#pragma unroll
            for (int h = 0; h < 2; h++) {
                const int row = m0 + warpM * 32 + mi * 16 + lr + h * 8;
                float r1x = acc1[mi][ni][h*2+0], r1y = acc1[mi][ni][h*2+1];
                if (LV == 3) {
                    r1x = fmaf(acc2[mi][ni][h*2+0], INV2048, r1x);
                    r1y = fmaf(acc2[mi][ni][h*2+1], INV2048, r1y);
                }
                float vx = fmaf(r1x, INV2048, acc0[mi][ni][h*2+0]) + bx;
                float vy = fmaf(r1y, INV2048, acc0[mi][ni][h*2+1]) + by;
                if (RELU) { vx = fmaxf(vx, 0.f); vy = fmaxf(vy, 0.f); }
                if (ADD) {
                    const float2 ci = *(const float2*)(Cin + (size_t)row * Ndim + col);
                    vx += ci.x; vy += ci.y;
                }
                *(float2*)(C + (size_t)row * Ndim + col) = make_float2(vx, vy);
            }
        }
    }
}

// ---------------- conv stem ----------------
__global__ void conv1_pool(const float* __restrict__ x, const float* __restrict__ w,
                           const float* __restrict__ bias, float* __restrict__ out) {
    __shared__ float ws[88];
    __shared__ float bsm[8];
    if (threadIdx.x < 88) ws[threadIdx.x] = w[threadIdx.x];
    if (threadIdx.x < 8)  bsm[threadIdx.x] = bias[threadIdx.x];
    __syncthreads();
    int idx = blockIdx.x * blockDim.x + threadIdx.x;
    if (idx >= NB * NL1) return;
    int b = idx >> 15, lo = idx & (NL1 - 1);
    const float* xb = x + (size_t)b * LRAW;
    float acc[8] = {0.f,0.f,0.f,0.f,0.f,0.f,0.f,0.f};
#pragma unroll
    for (int p = 0; p < 4; p++) {
        int l = 4 * lo + p;
        float conv[8];
#pragma unroll
        for (int c = 0; c < 8; c++) conv[c] = bsm[c];
#pragma unroll
        for (int j = 0; j < 11; j++) {
            int li = l + j - 5;
            float xv = (li >= 0 && li < LRAW) ? __ldg(&xb[li]) : 0.f;
#pragma unroll
            for (int c = 0; c < 8; c++) conv[c] += xv * ws[j * 8 + c];
        }
#pragma unroll
        for (int c = 0; c < 8; c++) acc[c] += fmaxf(conv[c], 0.f);
    }
#pragma unroll
    for (int c = 0; c < 8; c++) out[(size_t)idx * 8 + c] = acc[c] * 0.25f;
}

__global__ void conv2_pool(const float* __restrict__ in, const float* __restrict__ w,
                           const float* __restrict__ bias, float* __restrict__ out) {
    __shared__ float ws[384];
    __shared__ float bsm[16];
    for (int i = threadIdx.x; i < 384; i += blockDim.x) ws[i] = w[i];
    if (threadIdx.x < 16) bsm[threadIdx.x] = bias[threadIdx.x];
    __syncthreads();
    int idx = blockIdx.x * blockDim.x + threadIdx.x;
    if (idx >= NB * NL2) return;
    int b = idx >> 13, lo = idx & (NL2 - 1);
    float acc[16];
#pragma unroll
    for (int c = 0; c < 16; c++) acc[c] = 0.f;
#pragma unroll
    for (int p = 0; p < 4; p++) {
        int l = 4 * lo + p;
        float conv[16];
#pragma unroll
        for (int c = 0; c < 16; c++) conv[c] = bsm[c];
#pragma unroll
        for (int j = 0; j < 3; j++) {
            int li = l + j - 1;
            if (li >= 0 && li < NL1) {
                const float* row = in + ((size_t)b * NL1 + li) * 8;
#pragma unroll
                for (int ci = 0; ci < 8; ci++) {
                    float xv = __ldg(&row[ci]);
#pragma unroll
                    for (int co = 0; co < 16; co++) conv[co] += xv * ws[(j * 8 + ci) * 16 + co];
                }
            }
        }
#pragma unroll
        for (int c = 0; c < 16; c++) acc[c] += fmaxf(conv[c], 0.f);
    }
#pragma unroll
    for (int c = 0; c < 16; c++) out[(size_t)idx * 16 + c] = acc[c] * 0.25f;
}

// conv3: one block per (b, 16 consecutive lo); thread = output channel.
// Weights register-cached ONCE per block (amortized 16x vs old version); input rows
// staged in smem (broadcast reads). Same FMA order per output -> bit-identical results.
__global__ void conv3_pool(const float* __restrict__ in, const float* __restrict__ w,
                           const float* __restrict__ bias, float* __restrict__ out) {
    int blk = blockIdx.x;                 // NB * NS/16 = 1024
    int b = blk >> 7, lo0 = (blk & 127) * 16;
    int co = threadIdx.x;
    __shared__ float insm[66 * 16];
    for (int idx = threadIdx.x; idx < 66 * 16; idx += 256) {
        int rr = idx >> 4, ci = idx & 15;
        int li = 4 * lo0 - 1 + rr;
        insm[idx] = (li >= 0 && li < NL2) ? in[((size_t)b * NL2 + li) * 16 + ci] : 0.f;
    }
    float wreg[48];
#pragma unroll
    for (int i = 0; i < 48; i++) wreg[i] = __ldg(&w[(size_t)i * ND + co]);
    float bv = __ldg(&bias[co]);
    __syncthreads();
#pragma unroll 4
    for (int t = 0; t < 16; t++) {
        float acc = 0.f;
#pragma unroll
        for (int p = 0; p < 4; p++) {
            float conv = bv;
#pragma unroll
            for (int j = 0; j < 3; j++) {
#pragma unroll
                for (int ci = 0; ci < 16; ci++)
                    conv += insm[(4 * t + p + j) * 16 + ci] * wreg[j * 16 + ci];
            }
            acc += fmaxf(conv, 0.f);
        }
        out[((size_t)b * NS + lo0 + t) * ND + co] = acc * 0.25f;
    }
}

// ---------------- LayerCentering ----------------
__global__ void lc_kernel(const float* __restrict__ src, float* __restrict__ dst) {
    int row = blockIdx.x;
    int tid = threadIdx.x;
    float v = src[(size_t)row * ND + tid];
    float s = v;
#pragma unroll
    for (int off = 16; off; off >>= 1) s += __shfl_down_sync(0xffffffffu, s, off);
    __shared__ float red[8];
    __shared__ float meansh;
    if ((tid & 31) == 0) red[tid >> 5] = s;
    __syncthreads();
    if (tid == 0) {
        float t = 0.f;
#pragma unroll
        for (int i = 0; i < 8; i++) t += red[i];
        meansh = t * (1.0f / ND);
    }
    __syncthreads();
    dst[(size_t)row * ND + tid] = v - meansh;
}

// ---------------- fourier features + exponential positional modulation ----------------
__global__ void fourier_kernel(const float* __restrict__ q, const float* __restrict__ k,
                               const float* __restrict__ omega, const float* __restrict__ gamma,
                               float* __restrict__ qt, float* __restrict__ kt) {
    int bs = blockIdx.x;
    int tid = threadIdx.x;
    __shared__ float qrow[ND], krow[ND];
    qrow[tid] = q[(size_t)bs * ND + tid];
    krow[tid] = k[(size_t)bs * ND + tid];
    __syncthreads();
    int h = tid >> 5, lane = tid & 31;
    const float* om = omega + h * NDH * (NM / 2);
    float pq0 = 0.f, pq1 = 0.f, pk0 = 0.f, pk1 = 0.f;
#pragma unroll 8
    for (int d = 0; d < NDH; d++) {
        float qd = qrow[h * NDH + d], kd = krow[h * NDH + d];
        float o0 = __ldg(&om[d * 64 + lane]);
        float o1 = __ldg(&om[d * 64 + lane + 32]);
        pq0 += qd * o0; pq1 += qd * o1;
        pk0 += kd * o0; pk1 += kd * o1;
    }
    int s = bs & (NS - 1);
    float t = s * (1.0f / (NS - 1));
    float g = __ldg(&gamma[h]);
    float sl0 = 2.0f - lane * (1.0f / 32.0f);
    float sl1 = 2.0f - (lane + 32) * (1.0f / 32.0f);
    const float invs = 0.08838834764831845f;
    float a0 = g * t * sl0, a1 = g * t * sl1;
    float b0 = g * (1.0f - t) * sl0, b1 = g * (1.0f - t) * sl1;
    size_t base = ((size_t)bs * NH + h) * NM;
    qt[base + lane]      = cosf(pq0) * invs * expf(a0);
    qt[base + lane + 32] = cosf(pq1) * invs * expf(a1);
    qt[base + lane + 64] = sinf(pq0) * invs * expf(b0);
    qt[base + lane + 96] = sinf(pq1) * invs * expf(b1);
    kt[base + lane]      = cosf(pk0) * invs * expf(-a0);
    kt[base + lane + 32] = cosf(pk1) * invs * expf(-a1);
    kt[base + lane + 64] = sinf(pk0) * invs * expf(-b0);
    kt[base + lane + 96] = sinf(pk1) * invs * expf(-b1);
}

// ---------------- kv = sum_s kt^T v (split over S, deterministic) ----------------
__global__ void kv_partial(const float* __restrict__ kt, const float* __restrict__ v,
                           float* __restrict__ kvp) {
    int bh = blockIdx.x;
    int b = bh >> 3, h = bh & 7;
    int chunk = blockIdx.y;
    int m = threadIdx.x;
    __shared__ float vs[64 * 32];
    float acc[32];
#pragma unroll
    for (int e = 0; e < 32; e++) acc[e] = 0.f;
    int sbase = chunk * (NS / KV_SPLITS);
    for (int s0 = sbase; s0 < sbase + NS / KV_SPLITS; s0 += 64) {
        __syncthreads();
        for (int idx = threadIdx.x; idx < 64 * 32; idx += 128) {
            int i = idx >> 5, e = idx & 31;
            vs[idx] = v[((size_t)(b * NS + s0 + i)) * ND + h * NDH + e];
        }
        __syncthreads();
#pragma unroll 4
        for (int i = 0; i < 64; i++) {
            float kval = kt[(((size_t)(b * NS + s0 + i)) * NH + h) * NM + m];
#pragma unroll
            for (int e = 0; e < 32; e++) acc[e] += kval * vs[i * 32 + e];
        }
    }
    float* dst = kvp + (((size_t)chunk * (NB * NH) + bh) * NM + m) * NDH;
#pragma unroll
    for (int e = 0; e < 32; e++) dst[e] = acc[e];
}

__global__ void kv_reduce(const float* __restrict__ kvp, float* __restrict__ kv) {
    int idx = blockIdx.x * blockDim.x + threadIdx.x;
    if (idx >= NB * NH * NM * NDH) return;
    float s = 0.f;
#pragma unroll
    for (int c = 0; c < KV_SPLITS; c++) s += kvp[(size_t)c * (NB * NH * NM * NDH) + idx];
    kv[idx] = s;
}

// ---------------- o = qt @ kv ----------------
__global__ void attn_o(const float* __restrict__ qt, const float* __restrict__ kv,
                       float* __restrict__ o) {
    int bh = blockIdx.x;
    int b = bh >> 3, h = bh & 7;
    int s0 = blockIdx.y * 32;
    __shared__ float kvs[NM * NDH];
    __shared__ float qsm[32 * NM];
    for (int idx = threadIdx.x; idx < NM * NDH; idx += 256)
        kvs[idx] = kv[(size_t)bh * (NM * NDH) + idx];
    for (int idx = threadIdx.x; idx < 32 * NM; idx += 256) {
        int si = idx >> 7, m = idx & 127;
        qsm[idx] = qt[(((size_t)(b * NS + s0 + si)) * NH + h) * NM + m];
    }
    __syncthreads();
    int e = threadIdx.x & 31, sg = threadIdx.x >> 5;
    float acc[4] = {0.f, 0.f, 0.f, 0.f};
#pragma unroll 4
    for (int m = 0; m < NM; m++) {
        float kval = kvs[m * 32 + e];
#pragma unroll
        for (int i = 0; i < 4; i++) acc[i] += qsm[(sg * 4 + i) * NM + m] * kval;
    }
#pragma unroll
    for (int i = 0; i < 4; i++)
        o[((size_t)(b * NS + s0 + sg * 4 + i)) * ND + h * NDH + e] = acc[i];
}

// ---------------- host launcher ----------------
extern "C" void kernel_launch(void* const* d_in, const int* in_sizes, int n_in,
                              void* d_out, int out_size) {
    const float* x     = (const float*)d_in[0];
    const float* cw0   = (const float*)d_in[1];
    const float* cb0   = (const float*)d_in[2];
    const float* cw1   = (const float*)d_in[3];
    const float* cb1   = (const float*)d_in[4];
    const float* cw2   = (const float*)d_in[5];
    const float* cb2   = (const float*)d_in[6];
    const float* Wq    = (const float*)d_in[7];
    const float* bq    = (const float*)d_in[8];
    const float* Wk    = (const float*)d_in[9];
    const float* bk    = (const float*)d_in[10];
    const float* Wv    = (const float*)d_in[11];
    const float* bv    = (const float*)d_in[12];
    const float* Wo    = (const float*)d_in[13];
    const float* bo    = (const float*)d_in[14];
    const float* omega = (const float*)d_in[15];
    const float* gamma = (const float*)d_in[16];
    const float* W1    = (const float*)d_in[17];
    const float* b1    = (const float*)d_in[18];
    const float* W2    = (const float*)d_in[19];
    const float* b2    = (const float*)d_in[20];
    float* hout = (float*)d_out;

    float *p_h1, *p_h2, *p_ain, *p_q, *p_k, *p_v, *p_qt, *p_kt, *p_kv, *p_kvp, *p_o, *p_mid;
    uint32_t *p_wh, *p_wm, *p_wl;
    cudaGetSymbolAddress((void**)&p_h1,  g_h1);
    cudaGetSymbolAddress((void**)&p_h2,  g_h2);
    cudaGetSymbolAddress((void**)&p_ain, g_ain);
    cudaGetSymbolAddress((void**)&p_q,   g_q);
    cudaGetSymbolAddress((void**)&p_k,   g_k);
    cudaGetSymbolAddress((void**)&p_v,   g_v);
    cudaGetSymbolAddress((void**)&p_qt,  g_qt);
    cudaGetSymbolAddress((void**)&p_kt,  g_kt);
    cudaGetSymbolAddress((void**)&p_kv,  g_kv);
    cudaGetSymbolAddress((void**)&p_kvp, g_kvp);
    cudaGetSymbolAddress((void**)&p_o,   g_o);
    cudaGetSymbolAddress((void**)&p_mid, g_mid);
    cudaGetSymbolAddress((void**)&p_wh,  g_wh);
    cudaGetSymbolAddress((void**)&p_wm,  g_wm);
    cudaGetSymbolAddress((void**)&p_wl,  g_wl);

    cudaFuncSetAttribute(gemm_split<3, false, false>, cudaFuncAttributeMaxDynamicSharedMemorySize, GT_SMEM3);
    cudaFuncSetAttribute(gemm_split<2, false, false>, cudaFuncAttributeMaxDynamicSharedMemorySize, GT_SMEM2);
    cudaFuncSetAttribute(gemm_split<2, false, true>,  cudaFuncAttributeMaxDynamicSharedMemorySize, GT_SMEM2);
    cudaFuncSetAttribute(gemm_split<2, true, false>,  cudaFuncAttributeMaxDynamicSharedMemorySize, GT_SMEM2);

    // all weight splits in one launch (both layers, all 6 weights)
    wsplit_all<<<(TOT_KP + 255) / 256, 256>>>(Wq, Wk, Wv, Wo, W1, W2, p_wh, p_wm, p_wl);

    // conv stem
    conv1_pool<<<(NB * NL1 + 255) / 256, 256>>>(x, cw0, cb0, p_h1);
    conv2_pool<<<(NB * NL2 + 255) / 256, 256>>>(p_h1, cw1, cb1, p_h2);
    conv3_pool<<<NB * (NS / 16), 256>>>(p_h2, cw2, cb2, hout);

    dim3 gN256(4, NBS / 128);      // N=256
    dim3 gN1024(16, NBS / 128);    // N=1024

    constexpr int LSZ_S  = (ND / 2) * ND;
    constexpr int LSZ_W1 = (ND / 2) * NFF;
    constexpr int LSZ_W2 = (NFF / 2) * ND;

    for (int l = 0; l < 2; l++) {
        const int oQ = OFF_WQ + l * LSZ_S, oK = OFF_WK + l * LSZ_S;
        const int oV = OFF_WV + l * LSZ_S, oO = OFF_WO + l * LSZ_S;
        const int o1 = OFF_W1 + l * LSZ_W1, o2 = OFF_W2 + l * LSZ_W2;
        const float* om_l = omega + (size_t)l * NH * NDH * (NM / 2);
        const float* g_l  = gamma + (size_t)l * NH;

        lc_kernel<<<NBS, ND>>>(hout, p_ain);

        // ONLY Q,K (fourier operands) need the exact LV3 path.
        gemm_split<3, false, false><<<gN256, 256, GT_SMEM3>>>(p_ain, p_wh + oQ, p_wm + oQ, p_wl + oQ, bq + l * ND, nullptr, p_q, ND, ND);
        gemm_split<3, false, false><<<gN256, 256, GT_SMEM3>>>(p_ain, p_wh + oK, p_wm + oK, p_wl + oK, bk + l * ND, nullptr, p_k, ND, ND);
        gemm_split<2, false, false><<<gN256, 256, GT_SMEM2>>>(p_ain, p_wh + oV, p_wm + oV, p_wl + oV, bv + l * ND, nullptr, p_v, ND, ND);

        fourier_kernel<<<NBS, 256>>>(p_q, p_k, om_l, g_l, p_qt, p_kt);

        kv_partial<<<dim3(NB * NH, KV_SPLITS), 128>>>(p_kt, p_v, p_kvp);
        kv_reduce<<<(NB * NH * NM * NDH + 255) / 256, 256>>>(p_kvp, p_kv);

        attn_o<<<dim3(NB * NH, NS / 32), 256>>>(p_qt, p_kv, p_o);

        gemm_split<2, false, true><<<gN256, 256, GT_SMEM2>>>(p_o, p_wh + oO, p_wm + oO, p_wl + oO, bo + l * ND, hout, hout, ND, ND);

        lc_kernel<<<NBS, ND>>>(hout, p_ain);

        gemm_split<2, true, false><<<gN1024, 256, GT_SMEM2>>>(p_ain, p_wh + o1, p_wm + o1, p_wl + o1, b1 + l * NFF, nullptr, p_mid, NFF, ND);
        gemm_split<2, false, true><<<gN256, 256, GT_SMEM2>>>(p_mid, p_wh + o2, p_wm + o2, p_wl + o2, b2 + l * ND, hout, hout, ND, NFF);
    }
}